// round 1
// baseline (speedup 1.0000x reference)
#include <cuda_runtime.h>
#include <math.h>
#include <float.h>

#define Bx 2
#define Hx 8
#define Sx 1024
#define DH 64
#define DM 512
#define NT 33              // relative table rows actually reachable under causal mask
#define BHx (Bx*Hx)

// ---------------- scratch (static device globals; no allocation) ----------------
__device__ float g_table[NT][DH];
__device__ float g_q[BHx*Sx*DH];
__device__ float g_k[BHx*Sx*DH];
__device__ float g_v[BHx*Sx*DH];
__device__ float g_qrel[BHx*Sx*NT];
__device__ float g_prel[BHx*Sx*NT];
__device__ float g_s[(size_t)BHx*Sx*Sx];   // 64 MB scores/probs scratch
__device__ float g_o[BHx*Sx*DH];
__device__ float g_y[Bx*Sx*DM];

// ---------------- sin/cos table ----------------
__global__ void k_table() {
    int t = blockIdx.x;          // 0..32
    int j = threadIdx.x;         // 0..31
    float div = expf((2.0f * j) * (-logf(10000.0f) / (float)DH));
    float a = (float)t * div;
    g_table[t][2*j]   = sinf(a);
    g_table[t][2*j+1] = cosf(a);
}

// ---------------- QKV projection: out[b,h,s,d] = x @ W^T + bias ----------------
template<int WHICH>
__global__ void k_proj(const float* __restrict__ x, const float* __restrict__ W,
                       const float* __restrict__ bias) {
    __shared__ float As[64][33];
    __shared__ float Bs[64][33];
    float* out = (WHICH == 0) ? g_q : (WHICH == 1) ? g_k : g_v;
    int m0 = blockIdx.y * 64, n0 = blockIdx.x * 64;
    int tid = threadIdx.x;
    int tx = tid & 15, ty = tid >> 4;
    float acc[4][4] = {};
    for (int k0 = 0; k0 < DM; k0 += 32) {
        #pragma unroll
        for (int i = 0; i < 8; i++) {
            int idx = tid + i * 256;
            int m = idx >> 5, kk = idx & 31;
            As[m][kk] = x[(size_t)(m0 + m) * DM + k0 + kk];
            Bs[m][kk] = W[(size_t)(n0 + m) * DM + k0 + kk];
        }
        __syncthreads();
        #pragma unroll
        for (int kk = 0; kk < 32; kk++) {
            float a[4], b[4];
            #pragma unroll
            for (int i = 0; i < 4; i++) a[i] = As[ty*4+i][kk];
            #pragma unroll
            for (int j = 0; j < 4; j++) b[j] = Bs[tx*4+j][kk];
            #pragma unroll
            for (int i = 0; i < 4; i++)
                #pragma unroll
                for (int j = 0; j < 4; j++) acc[i][j] += a[i] * b[j];
        }
        __syncthreads();
    }
    #pragma unroll
    for (int i = 0; i < 4; i++) {
        int m = m0 + ty*4 + i;
        int b = m >> 10, s = m & 1023;
        #pragma unroll
        for (int j = 0; j < 4; j++) {
            int n = n0 + tx*4 + j;
            int h = n >> 6, d = n & 63;
            out[(((size_t)(b*Hx + h) * Sx + s) * DH) + d] = acc[i][j] + bias[n];
        }
    }
}

// ---------------- qrel[z,q,t] = q_vec . table[t] ----------------
__global__ void k_qrel() {
    int r = blockIdx.x;                 // z*Sx + q
    __shared__ float qv[DH];
    qv[threadIdx.x] = g_q[(size_t)r * DH + threadIdx.x];
    __syncthreads();
    int t = threadIdx.x;
    if (t < NT) {
        float s = 0.f;
        #pragma unroll
        for (int d = 0; d < DH; d++) s += qv[d] * g_table[t][d];
        g_qrel[(size_t)r * NT + t] = s;
    }
}

// ---------------- scores = (Q K^T + qrel gather) / 8, causal only ----------------
__global__ void k_scores() {
    int kb = blockIdx.x, qb = blockIdx.y, z = blockIdx.z;
    if (kb > qb) return;
    __shared__ float Qs[64][65];
    __shared__ float Ks[64][65];
    __shared__ float Rs[64][NT];
    int tid = threadIdx.x;
    int tx = tid & 15, ty = tid >> 4;
    const float* Q = g_q + ((size_t)z * Sx + qb*64) * DH;
    const float* K = g_k + ((size_t)z * Sx + kb*64) * DH;
    #pragma unroll
    for (int i = 0; i < 16; i++) {
        int idx = tid + i * 256;
        int m = idx >> 6, d = idx & 63;
        Qs[m][d] = Q[m*64 + d];
        Ks[m][d] = K[m*64 + d];
    }
    for (int idx = tid; idx < 64*NT; idx += 256) {
        int m = idx / NT, t = idx - m*NT;
        Rs[m][t] = g_qrel[((size_t)z*Sx + qb*64 + m) * NT + t];
    }
    __syncthreads();
    float acc[4][4] = {};
    #pragma unroll
    for (int d = 0; d < 64; d++) {
        float a[4], b[4];
        #pragma unroll
        for (int i = 0; i < 4; i++) a[i] = Qs[ty*4+i][d];
        #pragma unroll
        for (int j = 0; j < 4; j++) b[j] = Ks[tx*4+j][d];
        #pragma unroll
        for (int i = 0; i < 4; i++)
            #pragma unroll
            for (int j = 0; j < 4; j++) acc[i][j] += a[i] * b[j];
    }
    #pragma unroll
    for (int i = 0; i < 4; i++) {
        int q = qb*64 + ty*4 + i;
        #pragma unroll
        for (int j = 0; j < 4; j++) {
            int k = kb*64 + tx*4 + j;
            if (k <= q) {
                int dlt = k - q; if (dlt < -32) dlt = -32;
                float v = (acc[i][j] + Rs[ty*4+i][dlt + 32]) * 0.125f;
                g_s[((size_t)z*Sx + q) * Sx + k] = v;
            }
        }
    }
}

// ---------------- causal softmax per row + prel extraction ----------------
__global__ void k_softmax() {
    int r = blockIdx.x;
    int q = r & 1023;
    int tid = threadIdx.x;
    float* row = g_s + (size_t)r * Sx;
    int len = q + 1;
    __shared__ float red[256];

    float mx = -FLT_MAX;
    for (int k = tid; k < len; k += 256) mx = fmaxf(mx, row[k]);
    red[tid] = mx; __syncthreads();
    for (int s = 128; s > 0; s >>= 1) { if (tid < s) red[tid] = fmaxf(red[tid], red[tid+s]); __syncthreads(); }
    mx = red[0]; __syncthreads();

    float sum = 0.f, sum0 = 0.f;
    for (int k = tid; k < len; k += 256) {
        float e = expf(row[k] - mx);
        row[k] = e;
        sum += e;
        if (k <= q - 32) sum0 += e;
    }
    red[tid] = sum; __syncthreads();
    for (int s = 128; s > 0; s >>= 1) { if (tid < s) red[tid] += red[tid+s]; __syncthreads(); }
    float tot = red[0]; __syncthreads();
    red[tid] = sum0; __syncthreads();
    for (int s = 128; s > 0; s >>= 1) { if (tid < s) red[tid] += red[tid+s]; __syncthreads(); }
    float tot0 = red[0];

    float inv = 1.0f / tot;
    int kpad = (q/64 + 1) * 64;   // zero-fill masked tail of last 64-tile for the PV GEMM
    for (int k = tid; k < kpad; k += 256) row[k] = (k < len) ? row[k] * inv : 0.0f;
    __syncthreads();

    if (tid == 0) g_prel[(size_t)r * NT] = tot0 * inv;
    else if (tid <= 32) {
        int k = q - 32 + tid;
        g_prel[(size_t)r * NT + tid] = (k >= 0) ? row[k] : 0.0f;
    }
}

// ---------------- O = P @ V + prel @ table ----------------
__global__ void k_out() {
    int qb = blockIdx.x, z = blockIdx.y;
    __shared__ float Ps[64][65];
    __shared__ float Vs[64][65];
    int tid = threadIdx.x;
    int tx = tid & 15, ty = tid >> 4;
    float acc[4][4] = {};
    int kmax = qb*64 + 64;
    for (int k0 = 0; k0 < kmax; k0 += 64) {
        #pragma unroll
        for (int i = 0; i < 16; i++) {
            int idx = tid + i * 256;
            int m = idx >> 6, kk = idx & 63;
            Ps[m][kk] = g_s[((size_t)z*Sx + qb*64 + m) * Sx + k0 + kk];
            Vs[m][kk] = g_v[((size_t)z*Sx + k0 + m) * DH + kk];
        }
        __syncthreads();
        #pragma unroll
        for (int kk = 0; kk < 64; kk++) {
            float a[4], b[4];
            #pragma unroll
            for (int i = 0; i < 4; i++) a[i] = Ps[ty*4+i][kk];
            #pragma unroll
            for (int j = 0; j < 4; j++) b[j] = Vs[kk][tx*4+j];
            #pragma unroll
            for (int i = 0; i < 4; i++)
                #pragma unroll
                for (int j = 0; j < 4; j++) acc[i][j] += a[i] * b[j];
        }
        __syncthreads();
    }
    // relative-value term: reuse Ps (prel rows) and Vs (table)
    for (int idx = tid; idx < 64*NT; idx += 256) {
        int m = idx / NT, t = idx - m*NT;
        Ps[m][t] = g_prel[((size_t)z*Sx + qb*64 + m) * NT + t];
    }
    for (int idx = tid; idx < NT*64; idx += 256) {
        int t = idx >> 6, d = idx & 63;
        Vs[t][d] = g_table[t][d];
    }
    __syncthreads();
    #pragma unroll
    for (int t = 0; t < NT; t++) {
        float a[4], b[4];
        #pragma unroll
        for (int i = 0; i < 4; i++) a[i] = Ps[ty*4+i][t];
        #pragma unroll
        for (int j = 0; j < 4; j++) b[j] = Vs[t][tx*4+j];
        #pragma unroll
        for (int i = 0; i < 4; i++)
            #pragma unroll
            for (int j = 0; j < 4; j++) acc[i][j] += a[i] * b[j];
    }
    #pragma unroll
    for (int i = 0; i < 4; i++)
        #pragma unroll
        for (int j = 0; j < 4; j++)
            g_o[((size_t)z*Sx + qb*64 + ty*4 + i) * DH + tx*4 + j] = acc[i][j];
}

// ---------------- final proj + residual ----------------
__global__ void k_final(const float* __restrict__ Wo, const float* __restrict__ bo,
                        const float* __restrict__ resid) {
    __shared__ float As[64][33];
    __shared__ float Bs[64][33];
    int m0 = blockIdx.y * 64, n0 = blockIdx.x * 64;
    int tid = threadIdx.x;
    int tx = tid & 15, ty = tid >> 4;
    float acc[4][4] = {};
    for (int k0 = 0; k0 < DM; k0 += 32) {
        #pragma unroll
        for (int i = 0; i < 8; i++) {
            int idx = tid + i * 256;
            int m = idx >> 5, kk = idx & 31;
            int gm = m0 + m;
            int b = gm >> 10, s = gm & 1023;
            int gk = k0 + kk;
            int h = gk >> 6, d = gk & 63;
            As[m][kk] = g_o[(((size_t)(b*Hx + h) * Sx + s) * DH) + d];
            Bs[m][kk] = Wo[(size_t)(n0 + m) * DM + gk];
        }
        __syncthreads();
        #pragma unroll
        for (int kk = 0; kk < 32; kk++) {
            float a[4], b[4];
            #pragma unroll
            for (int i = 0; i < 4; i++) a[i] = As[ty*4+i][kk];
            #pragma unroll
            for (int j = 0; j < 4; j++) b[j] = Bs[tx*4+j][kk];
            #pragma unroll
            for (int i = 0; i < 4; i++)
                #pragma unroll
                for (int j = 0; j < 4; j++) acc[i][j] += a[i] * b[j];
        }
        __syncthreads();
    }
    #pragma unroll
    for (int i = 0; i < 4; i++) {
        int m = m0 + ty*4 + i;
        #pragma unroll
        for (int j = 0; j < 4; j++) {
            int n = n0 + tx*4 + j;
            g_y[(size_t)m * DM + n] = acc[i][j] + bo[n] + resid[(size_t)m * DM + n];
        }
    }
}

// ---------------- layernorm (ddof=1, divide by std+eps) ----------------
__global__ void k_ln(const float* __restrict__ w, const float* __restrict__ b,
                     float* __restrict__ out) {
    int m = blockIdx.x;
    int tid = threadIdx.x;
    const float* x = g_y + (size_t)m * DM;
    __shared__ float red[256];
    float x0 = x[tid], x1 = x[tid + 256];
    red[tid] = x0 + x1; __syncthreads();
    for (int s = 128; s > 0; s >>= 1) { if (tid < s) red[tid] += red[tid+s]; __syncthreads(); }
    float mean = red[0] * (1.0f / DM); __syncthreads();
    float d0 = x0 - mean, d1 = x1 - mean;
    red[tid] = d0*d0 + d1*d1; __syncthreads();
    for (int s = 128; s > 0; s >>= 1) { if (tid < s) red[tid] += red[tid+s]; __syncthreads(); }
    float var = red[0] * (1.0f / (DM - 1));
    float inv = 1.0f / (sqrtf(var) + 1e-6f);
    out[(size_t)m * DM + tid]       = w[tid]       * d0 * inv + b[tid];
    out[(size_t)m * DM + tid + 256] = w[tid + 256] * d1 * inv + b[tid + 256];
}

// ---------------- launch ----------------
extern "C" void kernel_launch(void* const* d_in, const int* in_sizes, int n_in,
                              void* d_out, int out_size) {
    const float* query = (const float*)d_in[0];
    const float* key   = (const float*)d_in[1];
    const float* value = (const float*)d_in[2];
    const float* Wq = (const float*)d_in[3];
    const float* bq = (const float*)d_in[4];
    const float* Wk = (const float*)d_in[5];
    const float* bk = (const float*)d_in[6];
    const float* Wv = (const float*)d_in[7];
    const float* bv = (const float*)d_in[8];
    const float* Wo = (const float*)d_in[9];
    const float* bo = (const float*)d_in[10];
    const float* ln_w = (const float*)d_in[11];
    const float* ln_b = (const float*)d_in[12];
    float* out = (float*)d_out;
    (void)in_sizes; (void)n_in; (void)out_size;

    k_table<<<NT, 32>>>();
    k_proj<0><<<dim3(DM/64, (Bx*Sx)/64), 256>>>(query, Wq, bq);
    k_proj<1><<<dim3(DM/64, (Bx*Sx)/64), 256>>>(key,   Wk, bk);
    k_proj<2><<<dim3(DM/64, (Bx*Sx)/64), 256>>>(value, Wv, bv);
    k_qrel<<<BHx*Sx, 64>>>();
    k_scores<<<dim3(Sx/64, Sx/64, BHx), 256>>>();
    k_softmax<<<BHx*Sx, 256>>>();
    k_out<<<dim3(Sx/64, BHx), 256>>>();
    k_final<<<dim3(DM/64, (Bx*Sx)/64), 256>>>(Wo, bo, query);
    k_ln<<<Bx*Sx, 256>>>(ln_w, ln_b, out);
}

// round 2
// speedup vs baseline: 1.1872x; 1.1872x over previous
#include <cuda_runtime.h>
#include <math.h>
#include <float.h>

#define Bx 2
#define Hx 8
#define Sx 1024
#define DH 64
#define DM 512
#define NT 33
#define BHx (Bx*Hx)

// ---------------- scratch ----------------
__device__ float g_table[NT][DH];
__device__ float g_q[BHx*Sx*DH];
__device__ float g_k[BHx*Sx*DH];
__device__ float g_v[BHx*Sx*DH];
__device__ float g_o[BHx*Sx*DH];
__device__ float g_y[Bx*Sx*DM];

// ---------------- sin/cos table ----------------
__global__ void k_table() {
    int t = blockIdx.x;
    int j = threadIdx.x;
    float div = expf((2.0f * j) * (-logf(10000.0f) / (float)DH));
    float a = (float)t * div;
    g_table[t][2*j]   = sinf(a);
    g_table[t][2*j+1] = cosf(a);
}

// ---------------- QKV projection: 128x64 tile, 8x4/thread ----------------
template<int WHICH>
__global__ void __launch_bounds__(256) k_proj(const float* __restrict__ x,
                                              const float* __restrict__ W,
                                              const float* __restrict__ bias) {
    __shared__ float As[128][33];
    __shared__ float Bs[64][33];
    float* out = (WHICH == 0) ? g_q : (WHICH == 1) ? g_k : g_v;
    int m0 = blockIdx.y * 128, n0 = blockIdx.x * 64;
    int tid = threadIdx.x;
    int tx = tid & 15, ty = tid >> 4;
    float acc[8][4] = {};
    for (int k0 = 0; k0 < DM; k0 += 32) {
        #pragma unroll
        for (int i = 0; i < 16; i++) {
            int idx = tid + i * 256;
            int m = idx >> 5, kk = idx & 31;
            As[m][kk] = x[(size_t)(m0 + m) * DM + k0 + kk];
        }
        #pragma unroll
        for (int i = 0; i < 8; i++) {
            int idx = tid + i * 256;
            int m = idx >> 5, kk = idx & 31;
            Bs[m][kk] = W[(size_t)(n0 + m) * DM + k0 + kk];
        }
        __syncthreads();
        #pragma unroll
        for (int kk = 0; kk < 32; kk++) {
            float a[8], b[4];
            #pragma unroll
            for (int i = 0; i < 8; i++) a[i] = As[ty*8+i][kk];
            #pragma unroll
            for (int j = 0; j < 4; j++) b[j] = Bs[tx*4+j][kk];
            #pragma unroll
            for (int i = 0; i < 8; i++)
                #pragma unroll
                for (int j = 0; j < 4; j++) acc[i][j] += a[i] * b[j];
        }
        __syncthreads();
    }
    #pragma unroll
    for (int i = 0; i < 8; i++) {
        int m = m0 + ty*8 + i;
        int b = m >> 10, s = m & 1023;
        #pragma unroll
        for (int j = 0; j < 4; j++) {
            int n = n0 + tx*4 + j;
            int h = n >> 6, d = n & 63;
            out[(((size_t)(b*Hx + h) * Sx + s) * DH) + d] = acc[i][j] + bias[n];
        }
    }
}

// ---------------- fused flash attention with relative positions ----------------
struct FlashSmem {
    float Qs[64][65];
    float Ks[64][65];   // also reused for table in epilogue
    float Vs[64][65];
    float Ps[64][65];   // probs for PV gemm; cols 0..32 reused for prel
    float band[64][32]; // raw scores for k in [q-31, q]
    float qrel[64][NT];
    float mrow[64];
    float lrow[64];
};

__device__ __forceinline__ void flash_qtile(FlashSmem* S, int z, int qb) {
    int tid = threadIdx.x;
    int tx = tid & 15, ty = tid >> 4;
    __syncthreads();  // protect smem from previous q-tile

    const size_t baseQ = ((size_t)z * Sx + qb*64) * DH;
    #pragma unroll
    for (int i = 0; i < 16; i++) {
        int idx = tid + i * 256;
        int m = idx >> 6, d = idx & 63;
        S->Qs[m][d] = g_q[baseQ + m*64 + d];
    }
    for (int idx = tid; idx < 64*32; idx += 256)
        S->band[idx >> 5][idx & 31] = -1e30f;
    __syncthreads();

    // qrel[m][t] = Q[m] . table[t]
    for (int idx = tid; idx < 64*NT; idx += 256) {
        int m = idx / NT, t = idx - m*NT;
        float s = 0.f;
        #pragma unroll
        for (int d = 0; d < DH; d++) s += S->Qs[m][d] * g_table[t][d];
        S->qrel[m][t] = s;
    }

    float acc[4][4] = {};
    float mr[4], lr[4];
    #pragma unroll
    for (int i = 0; i < 4; i++) { mr[i] = -1e30f; lr[i] = 0.f; }

    for (int kb = 0; kb <= qb; kb++) {
        __syncthreads();
        const size_t baseK = ((size_t)z * Sx + kb*64) * DH;
        #pragma unroll
        for (int i = 0; i < 16; i++) {
            int idx = tid + i * 256;
            int m = idx >> 6, d = idx & 63;
            S->Ks[m][d] = g_k[baseK + m*64 + d];
            S->Vs[m][d] = g_v[baseK + m*64 + d];
        }
        __syncthreads();

        float sacc[4][4] = {};
        #pragma unroll
        for (int d = 0; d < 64; d++) {
            float a[4], b[4];
            #pragma unroll
            for (int i = 0; i < 4; i++) a[i] = S->Qs[ty*4+i][d];
            #pragma unroll
            for (int j = 0; j < 4; j++) b[j] = S->Ks[tx*4+j][d];
            #pragma unroll
            for (int i = 0; i < 4; i++)
                #pragma unroll
                for (int j = 0; j < 4; j++) sacc[i][j] += a[i] * b[j];
        }

        // epilogue: mask + rel bias + online softmax
        #pragma unroll
        for (int i = 0; i < 4; i++) {
            int r = ty*4 + i;
            int q = qb*64 + r;
            float tmax = -1e30f;
            #pragma unroll
            for (int j = 0; j < 4; j++) {
                int k = kb*64 + tx*4 + j;
                float s;
                if (k <= q) {
                    int dlt = k - q; if (dlt < -32) dlt = -32;
                    s = (sacc[i][j] + S->qrel[r][dlt + 32]) * 0.125f;
                    int bi = k - q + 31;
                    if (bi >= 0) S->band[r][bi] = s;
                } else s = -1e30f;
                sacc[i][j] = s;
                tmax = fmaxf(tmax, s);
            }
            #pragma unroll
            for (int msk = 1; msk < 16; msk <<= 1)
                tmax = fmaxf(tmax, __shfl_xor_sync(0xffffffffu, tmax, msk));
            float mnew = fmaxf(mr[i], tmax);
            float cexp = __expf(mr[i] - mnew);
            float rs = 0.f;
            #pragma unroll
            for (int j = 0; j < 4; j++) {
                float pv = __expf(sacc[i][j] - mnew);
                rs += pv;
                S->Ps[r][tx*4+j] = pv;
            }
            #pragma unroll
            for (int msk = 1; msk < 16; msk <<= 1)
                rs += __shfl_xor_sync(0xffffffffu, rs, msk);
            lr[i] = lr[i] * cexp + rs;
            mr[i] = mnew;
            #pragma unroll
            for (int j = 0; j < 4; j++) acc[i][j] *= cexp;
        }
        __syncthreads();

        // O += P @ V
        #pragma unroll
        for (int kk = 0; kk < 64; kk++) {
            float a[4], b[4];
            #pragma unroll
            for (int i = 0; i < 4; i++) a[i] = S->Ps[ty*4+i][kk];
            #pragma unroll
            for (int j = 0; j < 4; j++) b[j] = S->Vs[kk][tx*4+j];
            #pragma unroll
            for (int i = 0; i < 4; i++)
                #pragma unroll
                for (int j = 0; j < 4; j++) acc[i][j] += a[i] * b[j];
        }
    }

    // normalize
    #pragma unroll
    for (int i = 0; i < 4; i++) {
        float inv = 1.0f / lr[i];
        #pragma unroll
        for (int j = 0; j < 4; j++) acc[i][j] *= inv;
    }
    if (tx == 0) {
        #pragma unroll
        for (int i = 0; i < 4; i++) {
            S->mrow[ty*4+i] = mr[i];
            S->lrow[ty*4+i] = lr[i];
        }
    }
    __syncthreads();

    // band probs -> Ps[r][1..32], clip-bucket mass -> Ps[r][0]
    if (tid < 64) {
        float m = S->mrow[tid];
        float inv = 1.0f / S->lrow[tid];
        float ssum = 0.f;
        #pragma unroll
        for (int t = 0; t < 32; t++) {
            float pv = __expf(S->band[tid][t] - m) * inv;
            S->Ps[tid][t+1] = pv;
            ssum += pv;
        }
        S->Ps[tid][0] = 1.0f - ssum;
    }
    // table into Ks
    for (int idx = tid; idx < NT*64; idx += 256)
        S->Ks[idx >> 6][idx & 63] = g_table[idx >> 6][idx & 63];
    __syncthreads();

    // O += prel @ table
    #pragma unroll
    for (int t = 0; t < NT; t++) {
        float a[4], b[4];
        #pragma unroll
        for (int i = 0; i < 4; i++) a[i] = S->Ps[ty*4+i][t];
        #pragma unroll
        for (int j = 0; j < 4; j++) b[j] = S->Ks[t][tx*4+j];
        #pragma unroll
        for (int i = 0; i < 4; i++)
            #pragma unroll
            for (int j = 0; j < 4; j++) acc[i][j] += a[i] * b[j];
    }
    #pragma unroll
    for (int i = 0; i < 4; i++)
        #pragma unroll
        for (int j = 0; j < 4; j++)
            g_o[((size_t)z*Sx + qb*64 + ty*4 + i) * DH + tx*4 + j] = acc[i][j];
}

__global__ void __launch_bounds__(256) k_flash() {
    extern __shared__ char smem_raw[];
    FlashSmem* S = (FlashSmem*)smem_raw;
    int z = blockIdx.y;
    flash_qtile(S, z, blockIdx.x);        // work = qb+1
    flash_qtile(S, z, 15 - blockIdx.x);   // work = 16-qb  -> uniform 17
}

// ---------------- final proj + residual: 128x64 tile, 8x4/thread ----------------
__global__ void __launch_bounds__(256) k_final(const float* __restrict__ Wo,
                                               const float* __restrict__ bo,
                                               const float* __restrict__ resid) {
    __shared__ float As[128][33];
    __shared__ float Bs[64][33];
    int m0 = blockIdx.y * 128, n0 = blockIdx.x * 64;
    int tid = threadIdx.x;
    int tx = tid & 15, ty = tid >> 4;
    float acc[8][4] = {};
    for (int k0 = 0; k0 < DM; k0 += 32) {
        #pragma unroll
        for (int i = 0; i < 16; i++) {
            int idx = tid + i * 256;
            int m = idx >> 5, kk = idx & 31;
            int gm = m0 + m;
            int b = gm >> 10, s = gm & 1023;
            int gk = k0 + kk;
            int h = gk >> 6, d = gk & 63;
            As[m][kk] = g_o[(((size_t)(b*Hx + h) * Sx + s) * DH) + d];
        }
        #pragma unroll
        for (int i = 0; i < 8; i++) {
            int idx = tid + i * 256;
            int m = idx >> 5, kk = idx & 31;
            Bs[m][kk] = Wo[(size_t)(n0 + m) * DM + k0 + kk];
        }
        __syncthreads();
        #pragma unroll
        for (int kk = 0; kk < 32; kk++) {
            float a[8], b[4];
            #pragma unroll
            for (int i = 0; i < 8; i++) a[i] = As[ty*8+i][kk];
            #pragma unroll
            for (int j = 0; j < 4; j++) b[j] = Bs[tx*4+j][kk];
            #pragma unroll
            for (int i = 0; i < 8; i++)
                #pragma unroll
                for (int j = 0; j < 4; j++) acc[i][j] += a[i] * b[j];
        }
        __syncthreads();
    }
    #pragma unroll
    for (int i = 0; i < 8; i++) {
        int m = m0 + ty*8 + i;
        #pragma unroll
        for (int j = 0; j < 4; j++) {
            int n = n0 + tx*4 + j;
            g_y[(size_t)m * DM + n] = acc[i][j] + bo[n] + resid[(size_t)m * DM + n];
        }
    }
}

// ---------------- layernorm (ddof=1, divide by std+eps) ----------------
__global__ void k_ln(const float* __restrict__ w, const float* __restrict__ b,
                     float* __restrict__ out) {
    int m = blockIdx.x;
    int tid = threadIdx.x;
    const float* x = g_y + (size_t)m * DM;
    __shared__ float red[256];
    float x0 = x[tid], x1 = x[tid + 256];
    red[tid] = x0 + x1; __syncthreads();
    for (int s = 128; s > 0; s >>= 1) { if (tid < s) red[tid] += red[tid+s]; __syncthreads(); }
    float mean = red[0] * (1.0f / DM); __syncthreads();
    float d0 = x0 - mean, d1 = x1 - mean;
    red[tid] = d0*d0 + d1*d1; __syncthreads();
    for (int s = 128; s > 0; s >>= 1) { if (tid < s) red[tid] += red[tid+s]; __syncthreads(); }
    float var = red[0] * (1.0f / (DM - 1));
    float inv = 1.0f / (sqrtf(var) + 1e-6f);
    out[(size_t)m * DM + tid]       = w[tid]       * d0 * inv + b[tid];
    out[(size_t)m * DM + tid + 256] = w[tid + 256] * d1 * inv + b[tid + 256];
}

// ---------------- launch ----------------
extern "C" void kernel_launch(void* const* d_in, const int* in_sizes, int n_in,
                              void* d_out, int out_size) {
    const float* query = (const float*)d_in[0];
    const float* key   = (const float*)d_in[1];
    const float* value = (const float*)d_in[2];
    const float* Wq = (const float*)d_in[3];
    const float* bq = (const float*)d_in[4];
    const float* Wk = (const float*)d_in[5];
    const float* bk = (const float*)d_in[6];
    const float* Wv = (const float*)d_in[7];
    const float* bv = (const float*)d_in[8];
    const float* Wo = (const float*)d_in[9];
    const float* bo = (const float*)d_in[10];
    const float* ln_w = (const float*)d_in[11];
    const float* ln_b = (const float*)d_in[12];
    float* out = (float*)d_out;
    (void)in_sizes; (void)n_in; (void)out_size;

    const int FLASH_SMEM = (int)sizeof(FlashSmem);
    cudaFuncSetAttribute(k_flash, cudaFuncAttributeMaxDynamicSharedMemorySize, FLASH_SMEM);

    k_table<<<NT, 32>>>();
    k_proj<0><<<dim3(DM/64, (Bx*Sx)/128), 256>>>(query, Wq, bq);
    k_proj<1><<<dim3(DM/64, (Bx*Sx)/128), 256>>>(key,   Wk, bk);
    k_proj<2><<<dim3(DM/64, (Bx*Sx)/128), 256>>>(value, Wv, bv);
    k_flash<<<dim3(8, BHx), 256, FLASH_SMEM>>>();
    k_final<<<dim3(DM/64, (Bx*Sx)/128), 256>>>(Wo, bo, query);
    k_ln<<<Bx*Sx, 256>>>(ln_w, ln_b, out);
}